// round 5
// baseline (speedup 1.0000x reference)
#include <cuda_runtime.h>
#include <cstdint>

// ---------------- problem dims (fixed by dataset) ----------------
#define S_LEN  512
#define BATCH  512
#define VOCAB  50000
#define EDIM   50
#define HDIM   128
#define G3     384          // 3*H
#define NROWS  1024         // 2 sequences * BATCH

typedef unsigned long long ull;

// ---------------- device scratch (no cudaMalloc allowed) ----------------
__device__ float g_emb_proj[(size_t)VOCAB * G3];   // 76.8 MB: W_ih @ emb[v] + b_ih
__device__ float g_hfinal[NROWS * HDIM];           // rows 0..511 = seq1, 512..1023 = seq2

// ---------------- helpers ----------------
__device__ __forceinline__ void ffma2(ull &acc, ull a, ull b) {
    asm("fma.rn.f32x2 %0, %1, %2, %0;" : "+l"(acc) : "l"(a), "l"(b));
}
__device__ __forceinline__ ull add2(ull a, ull b) {
    ull r; asm("add.rn.f32x2 %0, %1, %2;" : "=l"(r) : "l"(a), "l"(b)); return r;
}
__device__ __forceinline__ float lane_lo(ull v) { return __uint_as_float((unsigned)v); }
__device__ __forceinline__ float lane_hi(ull v) { return __uint_as_float((unsigned)(v >> 32)); }
__device__ __forceinline__ ull shfl_xor_ull(ull v, int m) {
    unsigned lo = __shfl_xor_sync(0xffffffffu, (unsigned)v, m);
    unsigned hi = __shfl_xor_sync(0xffffffffu, (unsigned)(v >> 32), m);
    return ((ull)hi << 32) | lo;
}
__device__ __forceinline__ float sigf(float x) {
    return __fdividef(1.f, 1.f + __expf(-x));
}
__device__ __forceinline__ float tanh_f(float x) {     // 2*sig(2x)-1, ~1e-6 err
    return __fdividef(2.f, 1.f + __expf(-2.f * x)) - 1.f;
}

// =================================================================
// Kernel A: emb_proj[v][g] = b_ih[g] + sum_e emb[v][e] * W_ih[g][e]
// 384 threads (thread = gate row g), 64 vocab rows per block.
// 4 independent accumulator chains (v-blocked) to break RAW latency.
// =================================================================
#define A_VB 64

__global__ __launch_bounds__(384) void emb_proj_kernel(
        const float* __restrict__ emb,
        const float* __restrict__ W_ih,
        const float* __restrict__ b_ih) {
    __shared__ __align__(16) float emb_s[A_VB * 52];   // padded pitch 52

    const int g  = threadIdx.x;                        // 0..383
    const int v0 = blockIdx.x * A_VB;

    for (int idx = g; idx < A_VB * EDIM; idx += 384) {
        int v = idx / EDIM, e = idx % EDIM;
        float val = 0.f;
        if (v0 + v < VOCAB) val = emb[(size_t)(v0 + v) * EDIM + e];
        emb_s[v * 52 + e] = val;
    }

    ull w2[25];
    const ull* wrow = reinterpret_cast<const ull*>(W_ih + g * EDIM);
#pragma unroll
    for (int ep = 0; ep < 25; ep++) w2[ep] = __ldg(&wrow[ep]);
    const float bias = __ldg(&b_ih[g]);

    __syncthreads();

    for (int vb = 0; vb < A_VB; vb += 4) {
        ull a0 = 0, a1 = 0, a2 = 0, a3 = 0;
        const ull* e0 = reinterpret_cast<const ull*>(&emb_s[(vb + 0) * 52]);
        const ull* e1 = reinterpret_cast<const ull*>(&emb_s[(vb + 1) * 52]);
        const ull* e2 = reinterpret_cast<const ull*>(&emb_s[(vb + 2) * 52]);
        const ull* e3 = reinterpret_cast<const ull*>(&emb_s[(vb + 3) * 52]);
#pragma unroll
        for (int ep = 0; ep < 25; ep++) {
            ull w = w2[ep];
            ffma2(a0, w, e0[ep]);
            ffma2(a1, w, e1[ep]);
            ffma2(a2, w, e2[ep]);
            ffma2(a3, w, e3[ep]);
        }
        float s0 = lane_lo(a0) + lane_hi(a0) + bias;
        float s1 = lane_lo(a1) + lane_hi(a1) + bias;
        float s2 = lane_lo(a2) + lane_hi(a2) + bias;
        float s3 = lane_lo(a3) + lane_hi(a3) + bias;
        if (v0 + vb + 0 < VOCAB) g_emb_proj[(size_t)(v0 + vb + 0) * G3 + g] = s0;
        if (v0 + vb + 1 < VOCAB) g_emb_proj[(size_t)(v0 + vb + 1) * G3 + g] = s1;
        if (v0 + vb + 2 < VOCAB) g_emb_proj[(size_t)(v0 + vb + 2) * G3 + g] = s2;
        if (v0 + vb + 3 < VOCAB) g_emb_proj[(size_t)(v0 + vb + 3) * G3 + g] = s3;
    }
}

// =================================================================
// Kernel B: persistent GRU. 128 CTAs x 8 rows, 384 threads.
// Thread (gq, kseg): gq = tid>>2 (gate quad, gates 4gq..4gq+3),
//                    kseg = tid&3 (K segment of 32).
// W SMEM interleaved for f32x2 gate-pair packing; h duplicated (h,h).
// In-warp shfl.bfly reduction over the 4 K-segments. 2 barriers/step.
//
// Dynamic SMEM (floats):
//   WS   [96*528]   202752 B   (pitch 528 = 4*132, conflict-free)
//   H2   [8*144] ull  9216 B   (dup h, kseg pitch 36 ull)
//   A_s  [8*384]    12288 B   (finalized pre-activations)
//   GXn  [8*128]     4096 B   (gx for n gates)
//   total          228352 B
// =================================================================
#define OFF_W    0
#define OFF_H2   50688                   // float index (ull region)
#define OFF_A    (OFF_H2 + 2304)         // 52992
#define OFF_GXN  (OFF_A + 3072)          // 56064
#define SMEM_FLOATS (OFF_GXN + 1024)     // 57088
#define SMEM_BYTES  (SMEM_FLOATS * 4)    // 228352

__global__ __launch_bounds__(384, 1) void gru_kernel(
        const int*   __restrict__ x1,
        const int*   __restrict__ x2,
        const float* __restrict__ W_hh,
        const float* __restrict__ b_hh) {
    extern __shared__ __align__(16) float sm[];
    float* WS  = sm + OFF_W;
    ull*   H2  = reinterpret_cast<ull*>(sm + OFF_H2);
    float* A_s = sm + OFF_A;
    float* GXn = sm + OFF_GXN;
    __shared__ int tok[8];

    const int tid  = threadIdx.x;
    const int gq   = tid >> 2;            // 0..95
    const int kseg = tid & 3;             // 0..3
    const int row0 = blockIdx.x * 8;
    const int rA   = 2 * kseg;            // finalize rows rA, rA+1

    // ---- stage W_hh into interleaved layout ----
    // dst(g,k): gq'=g>>2, p=(g>>1)&1, e=g&1, ks=k>>5, kl=k&31, c=kl>>1, dp=kl&1
    //   addr = gq'*528 + ks*132 + c*8 + p*4 + dp*2 + e
    for (int idx = tid; idx < G3 * HDIM; idx += 384) {
        int g = idx >> 7, k = idx & 127;
        int dgq = g >> 2, p = (g >> 1) & 1, e = g & 1;
        int ks = k >> 5, kl = k & 31, c = kl >> 1, dp = kl & 1;
        WS[dgq * 528 + ks * 132 + c * 8 + p * 4 + dp * 2 + e] = W_hh[idx];
    }
    // h = 0 (dup layout: H2[r*144 + ks*36 + kl])
    for (int idx = tid; idx < 8 * 144; idx += 384) H2[idx] = 0ull;
    if (tid < 8) {
        int row = row0 + tid;
        tok[tid] = (row < BATCH ? x1 : x2)[0 * BATCH + (row & (BATCH - 1))];
    }
    // per-thread bias float4 for gates 4gq..4gq+3
    const float4 b4 = __ldg(reinterpret_cast<const float4*>(&b_hh[4 * gq]));
    __syncthreads();

    const ull*  Wbase = reinterpret_cast<const ull*>(WS + gq * 528 + kseg * 132);
    const ulonglong2* Hbase = reinterpret_cast<const ulonglong2*>(H2 + kseg * 36);

    for (int t = 0; t < S_LEN; t++) {
        // ---- gather gx for this thread's 4 gates x finalize rows (hidden) ----
        float4 gx0 = __ldg(reinterpret_cast<const float4*>(
                           &g_emb_proj[(size_t)tok[rA] * G3 + 4 * gq]));
        float4 gx1 = __ldg(reinterpret_cast<const float4*>(
                           &g_emb_proj[(size_t)tok[rA + 1] * G3 + 4 * gq]));

        // ---- dot: accA = (g0,g1) partials, accB = (g2,g3), per row ----
        ull accA[8], accB[8];
#pragma unroll
        for (int r = 0; r < 8; r++) { accA[r] = 0ull; accB[r] = 0ull; }

#pragma unroll 4
        for (int c = 0; c < 16; c++) {             // 2 k-values per chunk
            ull wA0 = Wbase[c * 4 + 0];            // {W[g0][k0], W[g1][k0]}
            ull wA1 = Wbase[c * 4 + 1];            // {W[g0][k1], W[g1][k1]}
            ull wB0 = Wbase[c * 4 + 2];            // {W[g2][k0], W[g3][k0]}
            ull wB1 = Wbase[c * 4 + 3];            // {W[g2][k1], W[g3][k1]}
#pragma unroll
            for (int r = 0; r < 8; r++) {
                ulonglong2 hv = Hbase[r * 72 + c]; // {(hk0,hk0),(hk1,hk1)}
                ffma2(accA[r], wA0, hv.x);
                ffma2(accA[r], wA1, hv.y);
                ffma2(accB[r], wB0, hv.x);
                ffma2(accB[r], wB1, hv.y);
            }
        }

        // ---- in-warp reduce over the 4 K-segments (lanes xor 1,2) ----
#pragma unroll
        for (int r = 0; r < 8; r++) {
            accA[r] = add2(accA[r], shfl_xor_ull(accA[r], 1));
            accB[r] = add2(accB[r], shfl_xor_ull(accB[r], 1));
            accA[r] = add2(accA[r], shfl_xor_ull(accA[r], 2));
            accB[r] = add2(accB[r], shfl_xor_ull(accB[r], 2));
        }

        // ---- finalize rows rA, rA+1: add bias (+gx for r,z), publish ----
#pragma unroll
        for (int q = 0; q < 2; q++) {
            int r = rA + q;
            float f0 = lane_lo(accA[r]) + b4.x;
            float f1 = lane_hi(accA[r]) + b4.y;
            float f2 = lane_lo(accB[r]) + b4.z;
            float f3 = lane_hi(accB[r]) + b4.w;
            float4 gx = q ? gx1 : gx0;
            if (gq < 64) {                         // r,z gates: fold gx in
                f0 += gx.x; f1 += gx.y; f2 += gx.z; f3 += gx.w;
            } else {                               // n gates: gx kept separate
                *reinterpret_cast<float4*>(&GXn[r * HDIM + 4 * gq - 256]) = gx;
            }
            *reinterpret_cast<float4*>(&A_s[r * G3 + 4 * gq]) =
                make_float4(f0, f1, f2, f3);
        }
        __syncthreads();

        // ---- gate math + h update (1024 items / 384 threads) ----
        for (int item = tid; item < 8 * HDIM; item += 384) {
            int r = item >> 7, j = item & 127;
            float rr = sigf(A_s[r * G3 + j]);
            float zz = sigf(A_s[r * G3 + HDIM + j]);
            float nn = tanh_f(GXn[r * HDIM + j] + rr * A_s[r * G3 + 2 * HDIM + j]);
            int hidx = r * 144 + (j >> 5) * 36 + (j & 31);
            float hv = lane_lo(H2[hidx]);
            float hn = nn + zz * (hv - nn);
            unsigned hb = __float_as_uint(hn);
            H2[hidx] = ((ull)hb << 32) | hb;       // duplicated store
        }
        if (t + 1 < S_LEN && tid < 8) {
            int row = row0 + tid;
            tok[tid] = (row < BATCH ? x1 : x2)[(t + 1) * BATCH + (row & (BATCH - 1))];
        }
        __syncthreads();
    }

    // ---- write final hidden states ----
    for (int item = tid; item < 8 * HDIM; item += 384) {
        int r = item >> 7, j = item & 127;
        g_hfinal[(row0 + r) * HDIM + j] = lane_lo(H2[r * 144 + (j >> 5) * 36 + (j & 31)]);
    }
}

// =================================================================
// Kernel C: head.  out[b] = sigmoid( W2 . relu(W1 . [h1;h2] + b1) + b2 )
// =================================================================
__global__ __launch_bounds__(128) void head_kernel(
        const float* __restrict__ W1, const float* __restrict__ b1,
        const float* __restrict__ W2, const float* __restrict__ b2,
        float* __restrict__ out) {
    __shared__ float fc[2 * HDIM];
    __shared__ float red[HDIM];
    const int b = blockIdx.x, j = threadIdx.x;

    fc[j]        = g_hfinal[b * HDIM + j];
    fc[HDIM + j] = g_hfinal[(BATCH + b) * HDIM + j];
    __syncthreads();

    float acc = __ldg(&b1[j]);
    const float* wr = W1 + j * 2 * HDIM;
#pragma unroll 8
    for (int k = 0; k < 2 * HDIM; k++) acc = fmaf(fc[k], __ldg(&wr[k]), acc);
    float hid = fmaxf(acc, 0.f);

    red[j] = hid * __ldg(&W2[j]);
    __syncthreads();
    for (int s = 64; s > 0; s >>= 1) {
        if (j < s) red[j] += red[j + s];
        __syncthreads();
    }
    if (j == 0) out[b] = __fdividef(1.f, 1.f + __expf(-(red[0] + __ldg(&b2[0]))));
}

// =================================================================
// launch
// =================================================================
extern "C" void kernel_launch(void* const* d_in, const int* in_sizes, int n_in,
                              void* d_out, int out_size) {
    const int*   x1   = (const int*)  d_in[0];
    const int*   x2   = (const int*)  d_in[1];
    const float* emb  = (const float*)d_in[2];
    const float* W_ih = (const float*)d_in[3];
    const float* W_hh = (const float*)d_in[4];
    const float* b_ih = (const float*)d_in[5];
    const float* b_hh = (const float*)d_in[6];
    const float* W1   = (const float*)d_in[7];
    const float* b1   = (const float*)d_in[8];
    const float* W2   = (const float*)d_in[9];
    const float* b2   = (const float*)d_in[10];
    float* out = (float*)d_out;

    cudaFuncSetAttribute(gru_kernel,
                         cudaFuncAttributeMaxDynamicSharedMemorySize, SMEM_BYTES);

    const int a_blocks = (VOCAB + A_VB - 1) / A_VB;   // 782
    emb_proj_kernel<<<a_blocks, 384>>>(emb, W_ih, b_ih);
    gru_kernel<<<NROWS / 8, 384, SMEM_BYTES>>>(x1, x2, W_hh, b_hh);
    head_kernel<<<BATCH, 128>>>(W1, b1, W2, b2, out);
}

// round 6
// speedup vs baseline: 1.0570x; 1.0570x over previous
#include <cuda_runtime.h>
#include <cstdint>

// ---------------- problem dims (fixed by dataset) ----------------
#define S_LEN  512
#define BATCH  512
#define VOCAB  50000
#define EDIM   50
#define HDIM   128
#define G3     384          // 3*H
#define NROWS  1024         // 2 sequences * BATCH

typedef unsigned long long ull;

// ---------------- device scratch (no cudaMalloc allowed) ----------------
__device__ float g_emb_proj[(size_t)VOCAB * G3];   // 76.8 MB: W_ih @ emb[v] + b_ih
__device__ float g_hfinal[NROWS * HDIM];           // rows 0..511 = seq1, 512..1023 = seq2

// ---------------- helpers ----------------
__device__ __forceinline__ void ffma2(ull &acc, ull a, ull b) {
    asm("fma.rn.f32x2 %0, %1, %2, %0;" : "+l"(acc) : "l"(a), "l"(b));
}
__device__ __forceinline__ float lane_lo(ull v) { return __uint_as_float((unsigned)v); }
__device__ __forceinline__ float lane_hi(ull v) { return __uint_as_float((unsigned)(v >> 32)); }
__device__ __forceinline__ float sigf(float x) {
    return __fdividef(1.f, 1.f + __expf(-x));
}
__device__ __forceinline__ float tanh_f(float x) {     // 2*sig(2x)-1, ~1e-6 err
    return __fdividef(2.f, 1.f + __expf(-2.f * x)) - 1.f;
}

// =================================================================
// Kernel A: emb_proj[v][g] = b_ih[g] + sum_e emb[v][e] * W_ih[g][e]
// 384 threads (thread = gate row g), 64 vocab rows per block.
// =================================================================
#define A_VB 64

__global__ __launch_bounds__(384) void emb_proj_kernel(
        const float* __restrict__ emb,
        const float* __restrict__ W_ih,
        const float* __restrict__ b_ih) {
    __shared__ __align__(16) float emb_s[A_VB * 52];   // padded pitch 52

    const int g  = threadIdx.x;                        // 0..383
    const int v0 = blockIdx.x * A_VB;

    for (int idx = g; idx < A_VB * EDIM; idx += 384) {
        int v = idx / EDIM, e = idx % EDIM;
        float val = 0.f;
        if (v0 + v < VOCAB) val = emb[(size_t)(v0 + v) * EDIM + e];
        emb_s[v * 52 + e] = val;
    }

    ull w2[25];
    const ull* wrow = reinterpret_cast<const ull*>(W_ih + g * EDIM);
#pragma unroll
    for (int ep = 0; ep < 25; ep++) w2[ep] = __ldg(&wrow[ep]);
    const float bias = __ldg(&b_ih[g]);

    __syncthreads();

    for (int vb = 0; vb < A_VB; vb += 4) {
        ull a0 = 0, a1 = 0, a2 = 0, a3 = 0;
        const ull* e0 = reinterpret_cast<const ull*>(&emb_s[(vb + 0) * 52]);
        const ull* e1 = reinterpret_cast<const ull*>(&emb_s[(vb + 1) * 52]);
        const ull* e2 = reinterpret_cast<const ull*>(&emb_s[(vb + 2) * 52]);
        const ull* e3 = reinterpret_cast<const ull*>(&emb_s[(vb + 3) * 52]);
#pragma unroll
        for (int ep = 0; ep < 25; ep++) {
            ull w = w2[ep];
            ffma2(a0, w, e0[ep]);
            ffma2(a1, w, e1[ep]);
            ffma2(a2, w, e2[ep]);
            ffma2(a3, w, e3[ep]);
        }
        float s0 = lane_lo(a0) + lane_hi(a0) + bias;
        float s1 = lane_lo(a1) + lane_hi(a1) + bias;
        float s2 = lane_lo(a2) + lane_hi(a2) + bias;
        float s3 = lane_lo(a3) + lane_hi(a3) + bias;
        if (v0 + vb + 0 < VOCAB) g_emb_proj[(size_t)(v0 + vb + 0) * G3 + g] = s0;
        if (v0 + vb + 1 < VOCAB) g_emb_proj[(size_t)(v0 + vb + 1) * G3 + g] = s1;
        if (v0 + vb + 2 < VOCAB) g_emb_proj[(size_t)(v0 + vb + 2) * G3 + g] = s2;
        if (v0 + vb + 3 < VOCAB) g_emb_proj[(size_t)(v0 + vb + 3) * G3 + g] = s3;
    }
}

// =================================================================
// Kernel B: persistent GRU. 128 CTAs x 8 rows, 768 threads (24 warps).
// Row-split: warps 0-11 -> rows r0..r0+3 with r0=0, warps 12-23 -> r0=4.
// Thread = gate row g (tid mod 384); full K=128 dot per thread, NO
// cross-thread reduction. h loads are warp-broadcast LDS.128.
//
// Dynamic SMEM (floats):
//   WS   [384*132]  202752 B   (W_hh, pitch 132 -> conflict-free LDS.128)
//   h_s  [8*128]      4096 B
//   A_s  [8*384]     12288 B   (pre-activations; r,z have gx folded in)
//   GXn  [8*128]      4096 B   (gx for n gates)
//   tok  [8]            32 B
//   total           223264 B
// =================================================================
#define WPITCH 132
#define OFF_H    (G3 * WPITCH)           // 50688
#define OFF_A    (OFF_H + 8 * HDIM)      // 51712
#define OFF_GXN  (OFF_A + 8 * G3)        // 54784
#define OFF_TOK  (OFF_GXN + 8 * HDIM)    // 55808
#define SMEM_FLOATS (OFF_TOK + 8)        // 55816
#define SMEM_BYTES  (SMEM_FLOATS * 4)    // 223264

__global__ __launch_bounds__(768, 1) void gru_kernel(
        const int*   __restrict__ x1,
        const int*   __restrict__ x2,
        const float* __restrict__ W_hh,
        const float* __restrict__ b_hh) {
    extern __shared__ __align__(16) float sm[];
    float* WS  = sm;
    float* h_s = sm + OFF_H;
    float* A_s = sm + OFF_A;
    float* GXn = sm + OFF_GXN;
    int*   tok = (int*)(sm + OFF_TOK);

    const int tid  = threadIdx.x;
    const int half = tid >= 384;          // warps 0-11: half 0, 12-23: half 1
    const int g    = tid - half * 384;    // 0..383 (consecutive within warp)
    const int r0   = half * 4;            // first of this thread's 4 rows
    const int row0 = blockIdx.x * 8;

    // stage W_hh (384x128) into padded SMEM, coalesced
    for (int idx = tid; idx < G3 * HDIM; idx += 768) {
        int gg = idx >> 7, kk = idx & 127;
        WS[gg * WPITCH + kk] = W_hh[idx];
    }
    // h = 0
    for (int idx = tid; idx < 8 * HDIM; idx += 768) h_s[idx] = 0.f;
    // tokens for step 0
    if (tid < 8) {
        int row = row0 + tid;
        tok[tid] = (row < BATCH ? x1 : x2)[0 * BATCH + (row & (BATCH - 1))];
    }
    const float bhh = __ldg(&b_hh[g]);
    __syncthreads();

    const ulonglong2* Wrow = reinterpret_cast<const ulonglong2*>(WS + g * WPITCH);

    for (int t = 0; t < S_LEN; t++) {
        // ---- gather gx for this thread's gate x 4 rows (L2; hidden under dot) ----
        float gxv[4];
#pragma unroll
        for (int r = 0; r < 4; r++)
            gxv[r] = __ldg(&g_emb_proj[(size_t)tok[r0 + r] * G3 + g]);

        // ---- ghh[g][r] = sum_k W_hh[g][k] * h[r][k]  (packed f32x2) ----
        ull acc[4] = {0ull, 0ull, 0ull, 0ull};
#pragma unroll 8
        for (int kq = 0; kq < 32; kq++) {            // 4 floats per iter
            ulonglong2 w = Wrow[kq];                 // distinct rows: 4-cyc phases
#pragma unroll
            for (int r = 0; r < 4; r++) {            // broadcast h loads
                ulonglong2 hv = reinterpret_cast<const ulonglong2*>(
                                    h_s + (r0 + r) * HDIM)[kq];
                ffma2(acc[r], w.x, hv.x);
                ffma2(acc[r], w.y, hv.y);
            }
        }

        // ---- publish pre-activations ----
#pragma unroll
        for (int r = 0; r < 4; r++) {
            float a = lane_lo(acc[r]) + lane_hi(acc[r]) + bhh;
            int rr = r0 + r;
            if (g < 2 * HDIM) {
                A_s[rr * G3 + g] = a + gxv[r];       // r,z: fold gx in
            } else {
                A_s[rr * G3 + g] = a;                // n: ghh only
                GXn[rr * HDIM + (g - 2 * HDIM)] = gxv[r];
            }
        }
        __syncthreads();

        // ---- gate math + h update (1024 items / 768 threads) ----
        for (int item = tid; item < 8 * HDIM; item += 768) {
            int r = item >> 7, j = item & 127;
            float rr = sigf(A_s[r * G3 + j]);
            float zz = sigf(A_s[r * G3 + HDIM + j]);
            float nn = tanh_f(GXn[r * HDIM + j] + rr * A_s[r * G3 + 2 * HDIM + j]);
            float hv = h_s[item];
            h_s[item] = nn + zz * (hv - nn);
        }
        // tokens for next step (tok already consumed at top of this step)
        if (t + 1 < S_LEN && tid < 8) {
            int row = row0 + tid;
            tok[tid] = (row < BATCH ? x1 : x2)[(t + 1) * BATCH + (row & (BATCH - 1))];
        }
        __syncthreads();
    }

    // write final hidden states
    for (int item = tid; item < 8 * HDIM; item += 768) {
        int r = item >> 7, j = item & 127;
        g_hfinal[(row0 + r) * HDIM + j] = h_s[item];
    }
}

// =================================================================
// Kernel C: head.  out[b] = sigmoid( W2 . relu(W1 . [h1;h2] + b1) + b2 )
// =================================================================
__global__ __launch_bounds__(128) void head_kernel(
        const float* __restrict__ W1, const float* __restrict__ b1,
        const float* __restrict__ W2, const float* __restrict__ b2,
        float* __restrict__ out) {
    __shared__ float fc[2 * HDIM];
    __shared__ float red[HDIM];
    const int b = blockIdx.x, j = threadIdx.x;

    fc[j]        = g_hfinal[b * HDIM + j];
    fc[HDIM + j] = g_hfinal[(BATCH + b) * HDIM + j];
    __syncthreads();

    float acc = __ldg(&b1[j]);
    const float* wr = W1 + j * 2 * HDIM;
#pragma unroll 8
    for (int k = 0; k < 2 * HDIM; k++) acc = fmaf(fc[k], __ldg(&wr[k]), acc);
    float hid = fmaxf(acc, 0.f);

    red[j] = hid * __ldg(&W2[j]);
    __syncthreads();
    for (int s = 64; s > 0; s >>= 1) {
        if (j < s) red[j] += red[j + s];
        __syncthreads();
    }
    if (j == 0) out[b] = __fdividef(1.f, 1.f + __expf(-(red[0] + __ldg(&b2[0]))));
}

// =================================================================
// launch
// =================================================================
extern "C" void kernel_launch(void* const* d_in, const int* in_sizes, int n_in,
                              void* d_out, int out_size) {
    const int*   x1   = (const int*)  d_in[0];
    const int*   x2   = (const int*)  d_in[1];
    const float* emb  = (const float*)d_in[2];
    const float* W_ih = (const float*)d_in[3];
    const float* W_hh = (const float*)d_in[4];
    const float* b_ih = (const float*)d_in[5];
    const float* b_hh = (const float*)d_in[6];
    const float* W1   = (const float*)d_in[7];
    const float* b1   = (const float*)d_in[8];
    const float* W2   = (const float*)d_in[9];
    const float* b2   = (const float*)d_in[10];
    float* out = (float*)d_out;

    cudaFuncSetAttribute(gru_kernel,
                         cudaFuncAttributeMaxDynamicSharedMemorySize, SMEM_BYTES);

    const int a_blocks = (VOCAB + A_VB - 1) / A_VB;   // 782
    emb_proj_kernel<<<a_blocks, 384>>>(emb, W_ih, b_ih);
    gru_kernel<<<NROWS / 8, 768, SMEM_BYTES>>>(x1, x2, W_hh, b_hh);
    head_kernel<<<BATCH, 128>>>(W1, b1, W2, b2, out);
}

// round 7
// speedup vs baseline: 1.4771x; 1.3975x over previous
#include <cuda_runtime.h>
#include <cstdint>

// ---------------- problem dims (fixed by dataset) ----------------
#define S_LEN  512
#define BATCH  512
#define VOCAB  50000
#define EDIM   50
#define HDIM   128
#define G3     384          // 3*H
#define NROWS  1024         // 2 sequences * BATCH

// GRU kernel geometry: 147 CTAs x 7 rows covers 1029 >= 1024 rows
#define RPC    7            // rows per CTA
#define NCTA   147

typedef unsigned long long ull;

// ---------------- device scratch (no cudaMalloc allowed) ----------------
__device__ float g_emb_proj[(size_t)VOCAB * G3];   // 76.8 MB: W_ih @ emb[v] + b_ih
__device__ float g_hfinal[NROWS * HDIM];           // rows 0..511 = seq1, 512..1023 = seq2

// ---------------- helpers ----------------
__device__ __forceinline__ void ffma2(ull &acc, ull a, ull b) {
    asm("fma.rn.f32x2 %0, %1, %2, %0;" : "+l"(acc) : "l"(a), "l"(b));
}
__device__ __forceinline__ float lane_lo(ull v) { return __uint_as_float((unsigned)v); }
__device__ __forceinline__ float lane_hi(ull v) { return __uint_as_float((unsigned)(v >> 32)); }
__device__ __forceinline__ float sigf(float x) {
    return __fdividef(1.f, 1.f + __expf(-x));
}
__device__ __forceinline__ float tanh_f(float x) {     // 2*sig(2x)-1, ~1e-6 err
    return __fdividef(2.f, 1.f + __expf(-2.f * x)) - 1.f;
}

// =================================================================
// Kernel A: emb_proj[v][g] = b_ih[g] + sum_e emb[v][e] * W_ih[g][e]
// (unchanged from verified version)
// =================================================================
#define A_VB 64

__global__ __launch_bounds__(384) void emb_proj_kernel(
        const float* __restrict__ emb,
        const float* __restrict__ W_ih,
        const float* __restrict__ b_ih) {
    __shared__ __align__(16) float emb_s[A_VB * 52];   // padded pitch 52

    const int g  = threadIdx.x;                        // 0..383
    const int v0 = blockIdx.x * A_VB;

    for (int idx = g; idx < A_VB * EDIM; idx += 384) {
        int v = idx / EDIM, e = idx % EDIM;
        float val = 0.f;
        if (v0 + v < VOCAB) val = emb[(size_t)(v0 + v) * EDIM + e];
        emb_s[v * 52 + e] = val;
    }

    ull w2[25];
    const ull* wrow = reinterpret_cast<const ull*>(W_ih + g * EDIM);
#pragma unroll
    for (int ep = 0; ep < 25; ep++) w2[ep] = __ldg(&wrow[ep]);
    const float bias = __ldg(&b_ih[g]);

    __syncthreads();

    for (int vb = 0; vb < A_VB; vb += 4) {
        ull a0 = 0, a1 = 0, a2 = 0, a3 = 0;
        const ull* e0 = reinterpret_cast<const ull*>(&emb_s[(vb + 0) * 52]);
        const ull* e1 = reinterpret_cast<const ull*>(&emb_s[(vb + 1) * 52]);
        const ull* e2 = reinterpret_cast<const ull*>(&emb_s[(vb + 2) * 52]);
        const ull* e3 = reinterpret_cast<const ull*>(&emb_s[(vb + 3) * 52]);
#pragma unroll
        for (int ep = 0; ep < 25; ep++) {
            ull w = w2[ep];
            ffma2(a0, w, e0[ep]);
            ffma2(a1, w, e1[ep]);
            ffma2(a2, w, e2[ep]);
            ffma2(a3, w, e3[ep]);
        }
        float s0 = lane_lo(a0) + lane_hi(a0) + bias;
        float s1 = lane_lo(a1) + lane_hi(a1) + bias;
        float s2 = lane_lo(a2) + lane_hi(a2) + bias;
        float s3 = lane_lo(a3) + lane_hi(a3) + bias;
        if (v0 + vb + 0 < VOCAB) g_emb_proj[(size_t)(v0 + vb + 0) * G3 + g] = s0;
        if (v0 + vb + 1 < VOCAB) g_emb_proj[(size_t)(v0 + vb + 1) * G3 + g] = s1;
        if (v0 + vb + 2 < VOCAB) g_emb_proj[(size_t)(v0 + vb + 2) * G3 + g] = s2;
        if (v0 + vb + 3 < VOCAB) g_emb_proj[(size_t)(v0 + vb + 3) * G3 + g] = s3;
    }
}

// =================================================================
// Kernel B: persistent GRU. 147 CTAs x 7 rows, 384 threads (12 warps).
// Thread = gate row g. W_hh row held in 64 ull REGISTERS (no W SMEM
// stream). h broadcast from SMEM. No cross-thread reduction.
// Static SMEM ~18KB.
// =================================================================
__global__ __launch_bounds__(384, 1) void gru_kernel(
        const int*   __restrict__ x1,
        const int*   __restrict__ x2,
        const float* __restrict__ W_hh,
        const float* __restrict__ b_hh) {
    __shared__ __align__(16) float h_s[RPC * HDIM];    // 896 floats
    __shared__ __align__(16) float A_s[RPC * G3];      // 2688 floats
    __shared__ __align__(16) float GXn[RPC * HDIM];    // 896 floats
    __shared__ int tok[RPC];

    const int g    = threadIdx.x;          // 0..383 (gate row)
    const int row0 = blockIdx.x * RPC;

    // ---- W_hh[g][0..127] into registers (one-time) ----
    ull w2[64];
    {
        const ulonglong2* wrow =
            reinterpret_cast<const ulonglong2*>(W_hh + g * HDIM);
#pragma unroll
        for (int c = 0; c < 32; c++) {
            ulonglong2 v = __ldg(&wrow[c]);
            w2[2 * c]     = v.x;
            w2[2 * c + 1] = v.y;
        }
    }
    const float bhh = __ldg(&b_hh[g]);

    // h = 0
    for (int idx = g; idx < RPC * HDIM; idx += 384) h_s[idx] = 0.f;
    // tokens for step 0
    if (g < RPC) {
        int row = row0 + g; if (row > NROWS - 1) row = NROWS - 1;
        tok[g] = (row < BATCH) ? x1[row] : x2[row - BATCH];
    }
    __syncthreads();

    for (int t = 0; t < S_LEN; t++) {
        // ---- tokens -> gx gather (L2; hidden under dot loop) ----
        int tk[RPC];
#pragma unroll
        for (int r = 0; r < RPC; r++) tk[r] = tok[r];
        float gxv[RPC];
#pragma unroll
        for (int r = 0; r < RPC; r++)
            gxv[r] = __ldg(&g_emb_proj[(size_t)tk[r] * G3 + g]);

        // ---- ghh[g][r] = sum_k W[g][k] * h[r][k]  (W in regs, h broadcast) ----
        ull acc[RPC];
#pragma unroll
        for (int r = 0; r < RPC; r++) acc[r] = 0ull;

#pragma unroll
        for (int c = 0; c < 32; c++) {              // 4 floats per chunk
            ull wa = w2[2 * c], wb = w2[2 * c + 1];
#pragma unroll
            for (int r = 0; r < RPC; r++) {
                ulonglong2 hv = reinterpret_cast<const ulonglong2*>(
                                    h_s + r * HDIM)[c];
                ffma2(acc[r], wa, hv.x);
                ffma2(acc[r], wb, hv.y);
            }
        }

        // ---- publish pre-activations ----
#pragma unroll
        for (int r = 0; r < RPC; r++) {
            float a = lane_lo(acc[r]) + lane_hi(acc[r]) + bhh;
            if (g < 2 * HDIM) {
                A_s[r * G3 + g] = a + gxv[r];       // r,z: fold gx in
            } else {
                A_s[r * G3 + g] = a;                // n: ghh only
                GXn[r * HDIM + (g - 2 * HDIM)] = gxv[r];
            }
        }
        __syncthreads();

        // ---- gate math + h update (896 items / 384 threads) ----
        for (int item = g; item < RPC * HDIM; item += 384) {
            int r = item >> 7, j = item & 127;
            float rr = sigf(A_s[r * G3 + j]);
            float zz = sigf(A_s[r * G3 + HDIM + j]);
            float nn = tanh_f(GXn[r * HDIM + j] + rr * A_s[r * G3 + 2 * HDIM + j]);
            float hv = h_s[item];
            h_s[item] = nn + zz * (hv - nn);
        }
        // tokens for next step (current tok already consumed)
        if (t + 1 < S_LEN && g < RPC) {
            int row = row0 + g; if (row > NROWS - 1) row = NROWS - 1;
            tok[g] = (row < BATCH) ? x1[(t + 1) * BATCH + row]
                                   : x2[(t + 1) * BATCH + row - BATCH];
        }
        __syncthreads();
    }

    // write final hidden states (skip padded rows)
    for (int item = g; item < RPC * HDIM; item += 384) {
        int r = item >> 7, j = item & 127;
        int row = row0 + r;
        if (row < NROWS) g_hfinal[row * HDIM + j] = h_s[item];
    }
}

// =================================================================
// Kernel C: head.  out[b] = sigmoid( W2 . relu(W1 . [h1;h2] + b1) + b2 )
// =================================================================
__global__ __launch_bounds__(128) void head_kernel(
        const float* __restrict__ W1, const float* __restrict__ b1,
        const float* __restrict__ W2, const float* __restrict__ b2,
        float* __restrict__ out) {
    __shared__ float fc[2 * HDIM];
    __shared__ float red[HDIM];
    const int b = blockIdx.x, j = threadIdx.x;

    fc[j]        = g_hfinal[b * HDIM + j];
    fc[HDIM + j] = g_hfinal[(BATCH + b) * HDIM + j];
    __syncthreads();

    float acc = __ldg(&b1[j]);
    const float* wr = W1 + j * 2 * HDIM;
#pragma unroll 8
    for (int k = 0; k < 2 * HDIM; k++) acc = fmaf(fc[k], __ldg(&wr[k]), acc);
    float hid = fmaxf(acc, 0.f);

    red[j] = hid * __ldg(&W2[j]);
    __syncthreads();
    for (int s = 64; s > 0; s >>= 1) {
        if (j < s) red[j] += red[j + s];
        __syncthreads();
    }
    if (j == 0) out[b] = __fdividef(1.f, 1.f + __expf(-(red[0] + __ldg(&b2[0]))));
}

// =================================================================
// launch
// =================================================================
extern "C" void kernel_launch(void* const* d_in, const int* in_sizes, int n_in,
                              void* d_out, int out_size) {
    const int*   x1   = (const int*)  d_in[0];
    const int*   x2   = (const int*)  d_in[1];
    const float* emb  = (const float*)d_in[2];
    const float* W_ih = (const float*)d_in[3];
    const float* W_hh = (const float*)d_in[4];
    const float* b_ih = (const float*)d_in[5];
    const float* b_hh = (const float*)d_in[6];
    const float* W1   = (const float*)d_in[7];
    const float* b1   = (const float*)d_in[8];
    const float* W2   = (const float*)d_in[9];
    const float* b2   = (const float*)d_in[10];
    float* out = (float*)d_out;

    const int a_blocks = (VOCAB + A_VB - 1) / A_VB;   // 782
    emb_proj_kernel<<<a_blocks, 384>>>(emb, W_ih, b_ih);
    gru_kernel<<<NCTA, 384>>>(x1, x2, W_hh, b_hh);
    head_kernel<<<BATCH, 128>>>(W1, b1, W2, b2, out);
}